// round 11
// baseline (speedup 1.0000x reference)
#include <cuda_runtime.h>
#include <cuda_fp16.h>

// Problem constants (fixed by the reference: N=8, K=16, H=W=512, C=4, P=200000)
#define Nn 8
#define Kk 16
#define Hh 512
#define Ww 512
#define HW (Hh * Ww)
#define Pp 200000

// Truncation threshold. Measured: 1.5e-3 + fp16 table -> rel_err 5.97e-4,
// 1.67x under the 1e-3 gate (R10).
#define TCUT 1.5e-3f

// Scratch: ptclds transposed AND quantized to half4 (8B per point, 1.6 MB).
// Each gather L1 miss costs a 32B L2 sector; the small table doubles the
// random-access L1 hit rate vs fp32 (measured win in R9).
__device__ uint2 g_pth[Pp];

__global__ void transpose_pt_kernel(const float* __restrict__ pt)
{
    int i = blockIdx.x * blockDim.x + threadIdx.x;
    if (i < Pp) {
        __half2 lo = __floats2half2_rn(pt[i],          pt[Pp + i]);
        __half2 hi = __floats2half2_rn(pt[2 * Pp + i], pt[3 * Pp + i]);
        uint2 u;
        u.x = *reinterpret_cast<unsigned*>(&lo);
        u.y = *reinterpret_cast<unsigned*>(&hi);
        g_pth[i] = u;
    }
}

// Structure = R10 (best measured, 61.9us kernel) with ONE change: the gather
// loop is processed in chunks of 4 with explicit staging registers, so 4
// gathers are guaranteed in flight per warp before any is consumed
// (measured exposure: L1 at 72% with ~3 in flight; need more MLP, and
// R4/R6/R8 ruled out buying it with occupancy or 16-deep landing arrays).
// 5 blocks/SM (48-reg cap) gives the ~8 staging regs without spilling.
__global__ __launch_bounds__(256, 5)
void composite_kernel(const int*   __restrict__ frags,
                      const float* __restrict__ alphas,
                      const float* __restrict__ bg,
                      float*       __restrict__ out)
{
    int t = blockIdx.x * blockDim.x + threadIdx.x;
    int n = t >> 18;          // / (H*W)
    int p = t & (HW - 1);     // % (H*W)

    int base = n * (Kk * HW) + p;

    // Phase 0: ALL 32 streaming loads front-batched, unconditional, evict-first
    // (.cs keeps L1 ways free for the gather table; measured win in R10).
    int   f[Kk];
    float w[Kk];              // alphas land here, overwritten by weights
#pragma unroll
    for (int k = 0; k < Kk; k++) {
        f[k] = __ldcs(&frags [base + k * HW]);
        w[k] = __ldcs(&alphas[base + k * HW]);
    }

    // Phase 1: weight chain (serial FFMA/FSEL); pruned/invalid slots -> w=0.
    {
        float trans = 1.0f;
#pragma unroll
        for (int k = 0; k < Kk; k++) {
            float av = (f[k] >= 0) ? w[k] : 0.0f;
            w[k] = (trans >= TCUT) ? av * trans : 0.0f;
            trans *= (1.0f - av);
        }
    }

    // Phase 2: predicated 8B gathers in chunks of 4: all four loads issued
    // into staging regs before any conversion/FMA consumes them.
    float ax = 0.f, ay = 0.f, az = 0.f, aw = 0.f;
#pragma unroll
    for (int k = 0; k < Kk; k += 4) {
        uint2 r[4];
#pragma unroll
        for (int j = 0; j < 4; j++)
            if (w[k + j] > 0.0f) r[j] = __ldg(&g_pth[f[k + j]]);
#pragma unroll
        for (int j = 0; j < 4; j++) {
            if (w[k + j] > 0.0f) {
                float2 c01 = __half22float2(*reinterpret_cast<__half2*>(&r[j].x));
                float2 c23 = __half22float2(*reinterpret_cast<__half2*>(&r[j].y));
                ax += w[k + j] * c01.x;
                ay += w[k + j] * c01.y;
                az += w[k + j] * c23.x;
                aw += w[k + j] * c23.y;
            }
        }
    }

    // Pixels with no points get the background color (rgba, alpha=1).
    if (f[0] < 0) {
        ax = bg[0];
        ay = bg[1];
        az = bg[2];
        aw = 1.0f;
    }

    // NCHW output: 4 coalesced channel-plane stores (default policy).
    int ob = n * (4 * HW) + p;
    out[ob]          = ax;
    out[ob + HW]     = ay;
    out[ob + 2 * HW] = az;
    out[ob + 3 * HW] = aw;
}

extern "C" void kernel_launch(void* const* d_in, const int* in_sizes, int n_in,
                              void* d_out, int out_size)
{
    const int*   frags  = (const int*)  d_in[0];   // fragments (N,K,H,W) int32
    const float* alphas = (const float*)d_in[1];   // alphas    (N,K,H,W) f32
    const float* pt     = (const float*)d_in[2];   // ptclds    (C,P)     f32
    const float* bg     = (const float*)d_in[3];   // background_color (3,) f32
    float*       out    = (float*)d_out;           // (N,C,H,W) f32

    // 1) transpose + fp16-quantize ptclds (C,P) -> (P,4) half4 scratch
    transpose_pt_kernel<<<(Pp + 255) / 256, 256>>>(pt);

    // 2) composite: exactly N*H*W threads
    const int total = Nn * HW;                     // 2097152
    composite_kernel<<<total / 256, 256>>>(frags, alphas, bg, out);
}